// round 3
// baseline (speedup 1.0000x reference)
#include <cuda_runtime.h>
#include <math.h>
#include <float.h>

#define MAXN      (1 << 20)   // dist scratch capacity (N = 1e6 fits)
#define CAND_CAP  65536
#define KSEL      32
#define NBINS     4096
#define BIN_SCALE 1024.0f     // bins of width 1/1024 over [dmin, dmin+4)
#define MAXBLK    4096
#define FTHREADS  128

// ---- scratch (static device globals; no allocations anywhere) ----
__device__ float    g_dist[MAXN];
__device__ float    g_partsum[MAXBLK];
__device__ unsigned g_hist[NBINS];
__device__ unsigned g_dmin_bits;
__device__ float    g_thresh;
__device__ int      g_ncand;
__device__ float    g_cd[CAND_CAP];
__device__ int      g_ci[CAND_CAP];

// ---------------------------------------------------------------- init
__global__ void k_init() {
    int tid = threadIdx.x;
    for (int i = tid; i < NBINS; i += blockDim.x) g_hist[i] = 0u;
    if (tid == 0) {
        g_ncand = 0;
        g_dmin_bits = __float_as_uint(FLT_MAX);
        g_thresh = FLT_MAX;
    }
}

// ------------------------------------------------------- distances + Z
__global__ void k_dist(const float* __restrict__ X,
                       const float* __restrict__ q,
                       int N, int D) {
    __shared__ __align__(16) float sq[256];   // query cache (D <= 256 path)
    int tid = threadIdx.x;
    if (D <= 256) {
        for (int i = tid; i < D; i += blockDim.x) sq[i] = q[i];
    }
    __syncthreads();

    float lsum = 0.0f;
    float lmin = FLT_MAX;

    for (int i = blockIdx.x * blockDim.x + tid; i < N;
         i += gridDim.x * blockDim.x) {
        float acc = 0.0f;
        if (D == 64) {
            const float4* xp = (const float4*)(X + (size_t)i * 64);
            const float4* qp = (const float4*)sq;
            #pragma unroll
            for (int j = 0; j < 16; j++) {
                float4 v = xp[j];
                float4 w = qp[j];
                float d0 = v.x - w.x, d1 = v.y - w.y;
                float d2 = v.z - w.z, d3 = v.w - w.w;
                acc += d0 * d0 + d1 * d1 + d2 * d2 + d3 * d3;
            }
        } else {
            const float* xr = X + (size_t)i * D;
            for (int j = 0; j < D; j++) {
                float qv = (D <= 256) ? sq[j] : q[j];
                float d = xr[j] - qv;
                acc += d * d;
            }
        }
        float d = sqrtf(acc);
        g_dist[i] = d;
        lsum += expf(-d);          // TAU = 1
        lmin = fminf(lmin, d);
    }

    // block reduction (deterministic partials; no float atomics)
    __shared__ float ss[256];
    __shared__ float sm[256];
    ss[tid] = lsum;
    sm[tid] = lmin;
    __syncthreads();
    for (int s = blockDim.x >> 1; s > 0; s >>= 1) {
        if (tid < s) {
            ss[tid] += ss[tid + s];
            sm[tid] = fminf(sm[tid], sm[tid + s]);
        }
        __syncthreads();
    }
    if (tid == 0) {
        g_partsum[blockIdx.x] = ss[0];
        atomicMin(&g_dmin_bits, __float_as_uint(sm[0]));  // d >= 0: bits monotone
    }
}

// ------------------------------------------------------------ histogram
__global__ void k_hist(int N) {
    __shared__ unsigned sh[NBINS];
    for (int i = threadIdx.x; i < NBINS; i += blockDim.x) sh[i] = 0u;
    __syncthreads();

    float dmin = __uint_as_float(g_dmin_bits);
    for (int i = blockIdx.x * blockDim.x + threadIdx.x; i < N;
         i += gridDim.x * blockDim.x) {
        float d = g_dist[i];
        int b = (int)((d - dmin) * BIN_SCALE);
        b = b < 0 ? 0 : (b >= NBINS ? NBINS - 1 : b);
        atomicAdd(&sh[b], 1u);
    }
    __syncthreads();
    for (int i = threadIdx.x; i < NBINS; i += blockDim.x)
        if (sh[i]) atomicAdd(&g_hist[i], sh[i]);
}

// --------------------------------------------- threshold (cum >= KSEL)
__global__ void k_thresh(int N) {
    __shared__ unsigned sh[NBINS];
    __shared__ unsigned chunk[256];   // 16 bins each
    __shared__ unsigned super[32];    // 8 chunks each
    int tid = threadIdx.x;

    for (int i = tid; i < NBINS; i += 256) sh[i] = g_hist[i];
    __syncthreads();

    unsigned cs = 0;
    #pragma unroll
    for (int j = 0; j < 16; j++) cs += sh[tid * 16 + j];
    chunk[tid] = cs;
    __syncthreads();

    if (tid < 32) {
        unsigned s = 0;
        #pragma unroll
        for (int j = 0; j < 8; j++) s += chunk[tid * 8 + j];
        super[tid] = s;
    }
    __syncthreads();

    if (tid == 0) {
        if (N < KSEL) { g_thresh = FLT_MAX; return; }
        unsigned cum = 0;
        int sidx = 0;
        while (sidx < 32 && cum + super[sidx] < KSEL) { cum += super[sidx]; sidx++; }
        if (sidx == 32) { g_thresh = FLT_MAX; return; }
        int cidx = sidx * 8;
        while (cidx < (sidx + 1) * 8 && cum + chunk[cidx] < KSEL) { cum += chunk[cidx]; cidx++; }
        int b = cidx * 16;
        while (b < (cidx + 1) * 16 && cum + sh[b] < KSEL) { cum += sh[b]; b++; }
        if (b >= NBINS - 1) { g_thresh = FLT_MAX; return; }
        float dmin = __uint_as_float(g_dmin_bits);
        g_thresh = dmin + (float)(b + 1) / BIN_SCALE;   // inclusive upper edge
    }
}

// ------------------------------------------------------------ compact
__global__ void k_compact(int N) {
    float t = g_thresh;
    for (int i = blockIdx.x * blockDim.x + threadIdx.x; i < N;
         i += gridDim.x * blockDim.x) {
        float d = g_dist[i];
        if (d <= t) {
            int p = atomicAdd(&g_ncand, 1);
            if (p < CAND_CAP) { g_cd[p] = d; g_ci[p] = i; }
        }
    }
}

// ------------------------------------- final: Z, top-32 merge, output
__global__ void k_final(const float* __restrict__ y,
                        float* __restrict__ out,
                        int numPart, int DY, int Ntrain) {
    int tid = threadIdx.x;

    // --- reduce Z (deterministic) ---
    __shared__ float red[FTHREADS];
    float s = 0.0f;
    for (int i = tid; i < numPart; i += FTHREADS) s += g_partsum[i];
    red[tid] = s;
    __syncthreads();
    for (int st = FTHREADS >> 1; st > 0; st >>= 1) {
        if (tid < st) red[tid] += red[tid + st];
        __syncthreads();
    }
    __shared__ float sZ;
    if (tid == 0) sZ = red[0];
    __syncthreads();

    int ncand = g_ncand;
    if (ncand > CAND_CAP) ncand = CAND_CAP;

    // --- per-thread sorted top-KSEL (ties broken by smaller index) ---
    float td[KSEL];
    int   ti[KSEL];
    #pragma unroll
    for (int k = 0; k < KSEL; k++) { td[k] = FLT_MAX; ti[k] = 0x7fffffff; }

    for (int i = tid; i < ncand; i += FTHREADS) {
        float d = g_cd[i];
        int id = g_ci[i];
        if (d < td[KSEL - 1] || (d == td[KSEL - 1] && id < ti[KSEL - 1])) {
            int pos = KSEL - 1;
            while (pos > 0 &&
                   (td[pos - 1] > d || (td[pos - 1] == d && ti[pos - 1] > id))) {
                td[pos] = td[pos - 1];
                ti[pos] = ti[pos - 1];
                pos--;
            }
            td[pos] = d;
            ti[pos] = id;
        }
    }

    // --- dump per-thread lists, log2 tree merge ---
    __shared__ float md[FTHREADS * KSEL];   // 16 KB
    __shared__ int   mi[FTHREADS * KSEL];   // 16 KB
    #pragma unroll
    for (int k = 0; k < KSEL; k++) {
        md[tid * KSEL + k] = td[k];
        mi[tid * KSEL + k] = ti[k];
    }
    __syncthreads();

    for (int stride = 1; stride < FTHREADS; stride <<= 1) {
        if ((tid & (2 * stride - 1)) == 0) {
            int p = tid * KSEL;
            int q = (tid + stride) * KSEL;
            float od[KSEL];
            int   oi[KSEL];
            int ip = 0, iq = 0;
            #pragma unroll
            for (int k = 0; k < KSEL; k++) {
                float dp = md[p + ip], dq = md[q + iq];
                int   jp = mi[p + ip], jq = mi[q + iq];
                bool takep = (dp < dq) || (dp == dq && jp <= jq);
                if (takep) { od[k] = dp; oi[k] = jp; ip++; }
                else       { od[k] = dq; oi[k] = jq; iq++; }
            }
            #pragma unroll
            for (int k = 0; k < KSEL; k++) { md[p + k] = od[k]; mi[p + k] = oi[k]; }
        }
        __syncthreads();
    }

    // --- weights + gather-weighted sum over DY dims ---
    __shared__ float w[KSEL];
    __shared__ int   widx[KSEL];
    if (tid < KSEL) {
        w[tid] = expf(-md[tid]) / sZ;
        widx[tid] = mi[tid];
    }
    __syncthreads();

    for (int j = tid; j < DY; j += FTHREADS) {
        float acc = 0.0f;
        #pragma unroll
        for (int k = 0; k < KSEL; k++) {
            int id = widx[k];
            if ((unsigned)id < (unsigned)Ntrain)
                acc += w[k] * y[(size_t)id * DY + j];
        }
        out[j] = acc;
    }
}

// ---------------------------------------------------------------- host
extern "C" void kernel_launch(void* const* d_in, const int* in_sizes, int n_in,
                              void* d_out, int out_size) {
    const float* X = (const float*)d_in[0];
    const float* y = (const float*)d_in[1];
    const float* q = (const float*)d_in[2];

    int D = in_sizes[2];
    int N = in_sizes[0] / D;
    int DY = in_sizes[1] / N;
    float* out = (float*)d_out;

    int threads = 256;
    int blocks = (N + threads - 1) / threads;
    if (blocks > MAXBLK) blocks = MAXBLK;

    k_init<<<1, 256>>>();
    k_dist<<<blocks, threads>>>(X, q, N, D);
    k_hist<<<blocks, threads>>>(N);
    k_thresh<<<1, 256>>>(N);
    k_compact<<<blocks, threads>>>(N);
    k_final<<<1, FTHREADS>>>(y, out, blocks, DY, N);
}

// round 7
// speedup vs baseline: 1.2579x; 1.2579x over previous
#include <cuda_runtime.h>
#include <math.h>
#include <float.h>

#define MAXN      (1 << 20)   // dist scratch capacity (N = 1e6 fits)
#define CAND_CAP  65536
#define KSEL      32
#define NBINS     8192        // bins = float_bits(d) >> 18 (monotone for d >= 0)
#define BSHIFT    18
#define MAXBLK    4096
#define MERGE_T   128         // threads participating in top-K merge

// ---- scratch (static device globals; zero-initialized at module load) ----
__device__ float    g_dist[MAXN];
__device__ float    g_partsum[MAXBLK];
__device__ unsigned g_hist[NBINS];     // zero-init; reset by k_sel last block
__device__ float    g_Z;
__device__ int      g_bin_thresh;
__device__ int      g_ncand;           // zero-init; reset by k_sel last block
__device__ float    g_cd[CAND_CAP];
__device__ int      g_ci[CAND_CAP];
__device__ unsigned g_done1;           // zero-init; reset by k_dist last block
__device__ unsigned g_done2;           // zero-init; reset by k_sel last block

// ============================================================================
// Kernel 1: distances (coalesced), exp-sum partials, bit-histogram.
// Last block: reduce Z, find threshold bin.
// ============================================================================
__global__ void k_dist(const float* __restrict__ X, const float* __restrict__ q,
                       int N, int D) {
    __shared__ unsigned sh[NBINS];       // 32 KB: block-local hist, reused for scan
    __shared__ float4   sq4[16];
    __shared__ float    red[256];
    __shared__ unsigned chunk[256];
    __shared__ bool     amLast;

    int tid = threadIdx.x;
    for (int i = tid; i < NBINS; i += 256) sh[i] = 0u;
    if (D == 64 && tid < 16) sq4[tid] = ((const float4*)q)[tid];
    __syncthreads();

    float lsum = 0.0f;

    if (D == 64) {
        int lane = tid & 31;
        int wid  = blockIdx.x * (blockDim.x >> 5) + (tid >> 5);
        int nw   = gridDim.x * (blockDim.x >> 5);
        int col  = lane & 15;      // 16 lanes cover one 64-float row (16 x float4)
        int half = lane >> 4;      // 0 or 1: two rows per load instruction
        float4 qv = sq4[col];

        for (int base = wid * 8; base < N; base += nw * 8) {
            #pragma unroll
            for (int u = 0; u < 4; u++) {          // 8 rows / iter => 4 loads in flight
                int row = base + 2 * u + half;
                float4 v = qv;                      // OOB => diff 0 (result unused)
                if (row < N)
                    v = *(const float4*)(X + (size_t)row * 64 + col * 4);
                float d0 = v.x - qv.x, d1 = v.y - qv.y;
                float d2 = v.z - qv.z, d3 = v.w - qv.w;
                float acc = d0 * d0 + d1 * d1 + d2 * d2 + d3 * d3;
                acc += __shfl_xor_sync(0xffffffffu, acc, 8);
                acc += __shfl_xor_sync(0xffffffffu, acc, 4);
                acc += __shfl_xor_sync(0xffffffffu, acc, 2);
                acc += __shfl_xor_sync(0xffffffffu, acc, 1);
                if (col == 0 && row < N) {
                    float d = sqrtf(acc);
                    g_dist[row] = d;
                    lsum += expf(-d);               // TAU = 1
                    atomicAdd(&sh[__float_as_uint(d) >> BSHIFT], 1u);
                }
            }
        }
    } else {
        // generic fallback: thread-per-row
        for (int i = blockIdx.x * blockDim.x + tid; i < N;
             i += gridDim.x * blockDim.x) {
            float acc = 0.0f;
            const float* xr = X + (size_t)i * D;
            for (int j = 0; j < D; j++) { float d = xr[j] - q[j]; acc += d * d; }
            float d = sqrtf(acc);
            g_dist[i] = d;
            lsum += expf(-d);
            atomicAdd(&sh[__float_as_uint(d) >> BSHIFT], 1u);
        }
    }

    // block Z partial (deterministic)
    red[tid] = lsum;
    __syncthreads();
    for (int s = 128; s > 0; s >>= 1) {
        if (tid < s) red[tid] += red[tid + s];
        __syncthreads();
    }
    if (tid == 0) g_partsum[blockIdx.x] = red[0];

    // flush histogram
    for (int i = tid; i < NBINS; i += 256) {
        unsigned c = sh[i];
        if (c) atomicAdd(&g_hist[i], c);
    }

    // ---- last-block tail: Z reduce + threshold bin ----
    __threadfence();
    if (tid == 0) amLast = (atomicAdd(&g_done1, 1u) == (unsigned)gridDim.x - 1u);
    __syncthreads();
    if (!amLast) return;

    float s2 = 0.0f;
    for (int i = tid; i < gridDim.x; i += 256) s2 += g_partsum[i];
    red[tid] = s2;
    __syncthreads();
    for (int s = 128; s > 0; s >>= 1) {
        if (tid < s) red[tid] += red[tid + s];
        __syncthreads();
    }
    if (tid == 0) g_Z = red[0];

    for (int i = tid; i < NBINS; i += 256) sh[i] = g_hist[i];
    __syncthreads();
    unsigned cs = 0;
    #pragma unroll
    for (int j = 0; j < 32; j++) cs += sh[tid * 32 + j];
    chunk[tid] = cs;
    __syncthreads();

    if (tid == 0) {
        unsigned target = (unsigned)(N < KSEL ? N : KSEL);
        unsigned cum = 0;
        int c = 0;
        while (c < 256 && cum + chunk[c] < target) { cum += chunk[c]; c++; }
        int b;
        if (c == 256) b = NBINS - 1;
        else {
            b = c * 32;
            while (b < (c + 1) * 32 && cum + sh[b] < target) { cum += sh[b]; b++; }
            if (b >= NBINS) b = NBINS - 1;
        }
        g_bin_thresh = b;
        g_done1 = 0;                 // reset for next graph replay
    }
}

// ============================================================================
// Kernel 2: compact candidates (bits compare), last block does top-K + output
// and resets all scratch for the next replay.
// ============================================================================
__global__ void k_sel(const float* __restrict__ y, float* __restrict__ out,
                      int N, int DY) {
    __shared__ float md[MERGE_T * KSEL];   // 16 KB
    __shared__ int   mi[MERGE_T * KSEL];   // 16 KB
    __shared__ float w[KSEL];
    __shared__ int   widx[KSEL];
    __shared__ float sZ;
    __shared__ bool  amLast;

    int tid = threadIdx.x;
    unsigned limit = ((unsigned)(g_bin_thresh + 1)) << BSHIFT;  // bits < limit <=> bin <= thresh

    int n4 = N >> 2;
    const float4* d4 = (const float4*)g_dist;
    for (int i = blockIdx.x * blockDim.x + tid; i < n4;
         i += gridDim.x * blockDim.x) {
        float4 v = d4[i];
        if (__float_as_uint(v.x) < limit) { int p = atomicAdd(&g_ncand, 1); if (p < CAND_CAP) { g_cd[p] = v.x; g_ci[p] = 4 * i;     } }
        if (__float_as_uint(v.y) < limit) { int p = atomicAdd(&g_ncand, 1); if (p < CAND_CAP) { g_cd[p] = v.y; g_ci[p] = 4 * i + 1; } }
        if (__float_as_uint(v.z) < limit) { int p = atomicAdd(&g_ncand, 1); if (p < CAND_CAP) { g_cd[p] = v.z; g_ci[p] = 4 * i + 2; } }
        if (__float_as_uint(v.w) < limit) { int p = atomicAdd(&g_ncand, 1); if (p < CAND_CAP) { g_cd[p] = v.w; g_ci[p] = 4 * i + 3; } }
    }
    if (blockIdx.x == 0 && tid == 0) {           // scalar tail (N % 4)
        for (int i = n4 * 4; i < N; i++) {
            float d = g_dist[i];
            if (__float_as_uint(d) < limit) {
                int p = atomicAdd(&g_ncand, 1);
                if (p < CAND_CAP) { g_cd[p] = d; g_ci[p] = i; }
            }
        }
    }

    __threadfence();
    if (tid == 0) amLast = (atomicAdd(&g_done2, 1u) == (unsigned)gridDim.x - 1u);
    __syncthreads();
    if (!amLast) return;

    // ---- final: top-KSEL merge (index tie-break matches jax top_k), output ----
    if (tid == 0) sZ = g_Z;
    int ncand = g_ncand;
    if (ncand > CAND_CAP) ncand = CAND_CAP;
    __syncthreads();

    float td[KSEL];
    int   ti[KSEL];
    if (tid < MERGE_T) {
        #pragma unroll
        for (int k = 0; k < KSEL; k++) { td[k] = FLT_MAX; ti[k] = 0x7fffffff; }
        for (int i = tid; i < ncand; i += MERGE_T) {
            float d = g_cd[i];
            int id = g_ci[i];
            if (d < td[KSEL - 1] || (d == td[KSEL - 1] && id < ti[KSEL - 1])) {
                int pos = KSEL - 1;
                while (pos > 0 &&
                       (td[pos - 1] > d || (td[pos - 1] == d && ti[pos - 1] > id))) {
                    td[pos] = td[pos - 1]; ti[pos] = ti[pos - 1]; pos--;
                }
                td[pos] = d; ti[pos] = id;
            }
        }
        #pragma unroll
        for (int k = 0; k < KSEL; k++) {
            md[tid * KSEL + k] = td[k];
            mi[tid * KSEL + k] = ti[k];
        }
    }
    __syncthreads();

    for (int stride = 1; stride < MERGE_T; stride <<= 1) {
        if (tid < MERGE_T && (tid & (2 * stride - 1)) == 0) {
            int p = tid * KSEL;
            int qq = (tid + stride) * KSEL;
            float od[KSEL];
            int   oi[KSEL];
            int ip = 0, iq = 0;
            #pragma unroll
            for (int k = 0; k < KSEL; k++) {
                float dp = md[p + ip], dq = md[qq + iq];
                int   jp = mi[p + ip], jq = mi[qq + iq];
                bool takep = (dp < dq) || (dp == dq && jp <= jq);
                if (takep) { od[k] = dp; oi[k] = jp; ip++; }
                else       { od[k] = dq; oi[k] = jq; iq++; }
            }
            #pragma unroll
            for (int k = 0; k < KSEL; k++) { md[p + k] = od[k]; mi[p + k] = oi[k]; }
        }
        __syncthreads();
    }

    if (tid < KSEL) {
        w[tid] = expf(-md[tid]) / sZ;      // expf(-FLT_MAX) == 0 for padding
        widx[tid] = mi[tid];
    }
    __syncthreads();

    for (int j = tid; j < DY; j += blockDim.x) {
        float acc = 0.0f;
        #pragma unroll
        for (int k = 0; k < KSEL; k++) {
            int id = widx[k];
            if ((unsigned)id < (unsigned)N)
                acc += w[k] * y[(size_t)id * DY + j];
        }
        out[j] = acc;
    }

    // ---- reset scratch for next graph replay ----
    for (int i = tid; i < NBINS; i += blockDim.x) g_hist[i] = 0u;
    if (tid == 0) { g_ncand = 0; g_done2 = 0; }
}

// ---------------------------------------------------------------- host
extern "C" void kernel_launch(void* const* d_in, const int* in_sizes, int n_in,
                              void* d_out, int out_size) {
    const float* X = (const float*)d_in[0];
    const float* y = (const float*)d_in[1];
    const float* q = (const float*)d_in[2];

    int D  = in_sizes[2];
    int N  = in_sizes[0] / D;
    int DY = in_sizes[1] / N;
    float* out = (float*)d_out;

    int b1 = 1536;
    int need1 = (D == 64) ? (N + 63) / 64 : (N + 255) / 256;
    if (need1 < b1) b1 = need1;
    if (b1 < 1) b1 = 1;
    if (b1 > MAXBLK) b1 = MAXBLK;

    int b2 = 512;
    int need2 = (N / 4 + 255) / 256;
    if (need2 < b2) b2 = need2;
    if (b2 < 1) b2 = 1;

    k_dist<<<b1, 256>>>(X, q, N, D);
    k_sel<<<b2, 256>>>(y, out, N, DY);
}

// round 8
// speedup vs baseline: 1.4924x; 1.1864x over previous
#include <cuda_runtime.h>
#include <math.h>
#include <float.h>

#define MAXN      (1 << 20)   // dist scratch capacity (N = 1e6 fits)
#define CAND_CAP  65536
#define KSEL      32
#define NBINS     8192        // bins = float_bits(d) >> 18 (monotone for d >= 0)
#define BSHIFT    18
#define MAXBLK    4096
#define MERGE_T   128         // threads in fallback merge
#define SORT_CAP  2048        // bitonic path capacity (u64 keys, 16 KB)

// ---- scratch (static device globals; zero-initialized at module load) ----
__device__ float    g_dist[MAXN];
__device__ float    g_partsum[MAXBLK];
__device__ unsigned g_hist[NBINS];     // zero-init; reset by k_sel last block
__device__ float    g_Z;
__device__ int      g_bin_thresh;
__device__ int      g_ncand;           // zero-init; reset by k_sel last block
__device__ float    g_cd[CAND_CAP];
__device__ int      g_ci[CAND_CAP];
__device__ unsigned g_done1;           // zero-init; reset by k_dist last block
__device__ unsigned g_done2;           // zero-init; reset by k_sel last block

// ============================================================================
// Kernel 1: distances (coalesced), exp-sum partials, bit-histogram.
// Last block: reduce Z, find threshold bin.  (unchanged from R6)
// ============================================================================
__global__ void k_dist(const float* __restrict__ X, const float* __restrict__ q,
                       int N, int D) {
    __shared__ unsigned sh[NBINS];       // 32 KB: block-local hist, reused for scan
    __shared__ float4   sq4[16];
    __shared__ float    red[256];
    __shared__ unsigned chunk[256];
    __shared__ bool     amLast;

    int tid = threadIdx.x;
    for (int i = tid; i < NBINS; i += 256) sh[i] = 0u;
    if (D == 64 && tid < 16) sq4[tid] = ((const float4*)q)[tid];
    __syncthreads();

    float lsum = 0.0f;

    if (D == 64) {
        int lane = tid & 31;
        int wid  = blockIdx.x * (blockDim.x >> 5) + (tid >> 5);
        int nw   = gridDim.x * (blockDim.x >> 5);
        int col  = lane & 15;      // 16 lanes cover one 64-float row (16 x float4)
        int half = lane >> 4;      // 0 or 1: two rows per load instruction
        float4 qv = sq4[col];

        for (int base = wid * 8; base < N; base += nw * 8) {
            #pragma unroll
            for (int u = 0; u < 4; u++) {          // 8 rows / iter => 4 loads in flight
                int row = base + 2 * u + half;
                float4 v = qv;                      // OOB => diff 0 (result unused)
                if (row < N)
                    v = *(const float4*)(X + (size_t)row * 64 + col * 4);
                float d0 = v.x - qv.x, d1 = v.y - qv.y;
                float d2 = v.z - qv.z, d3 = v.w - qv.w;
                float acc = d0 * d0 + d1 * d1 + d2 * d2 + d3 * d3;
                acc += __shfl_xor_sync(0xffffffffu, acc, 8);
                acc += __shfl_xor_sync(0xffffffffu, acc, 4);
                acc += __shfl_xor_sync(0xffffffffu, acc, 2);
                acc += __shfl_xor_sync(0xffffffffu, acc, 1);
                if (col == 0 && row < N) {
                    float d = sqrtf(acc);
                    g_dist[row] = d;
                    lsum += expf(-d);               // TAU = 1
                    atomicAdd(&sh[__float_as_uint(d) >> BSHIFT], 1u);
                }
            }
        }
    } else {
        for (int i = blockIdx.x * blockDim.x + tid; i < N;
             i += gridDim.x * blockDim.x) {
            float acc = 0.0f;
            const float* xr = X + (size_t)i * D;
            for (int j = 0; j < D; j++) { float d = xr[j] - q[j]; acc += d * d; }
            float d = sqrtf(acc);
            g_dist[i] = d;
            lsum += expf(-d);
            atomicAdd(&sh[__float_as_uint(d) >> BSHIFT], 1u);
        }
    }

    red[tid] = lsum;
    __syncthreads();
    for (int s = 128; s > 0; s >>= 1) {
        if (tid < s) red[tid] += red[tid + s];
        __syncthreads();
    }
    if (tid == 0) g_partsum[blockIdx.x] = red[0];

    for (int i = tid; i < NBINS; i += 256) {
        unsigned c = sh[i];
        if (c) atomicAdd(&g_hist[i], c);
    }

    __threadfence();
    if (tid == 0) amLast = (atomicAdd(&g_done1, 1u) == (unsigned)gridDim.x - 1u);
    __syncthreads();
    if (!amLast) return;

    float s2 = 0.0f;
    for (int i = tid; i < gridDim.x; i += 256) s2 += g_partsum[i];
    red[tid] = s2;
    __syncthreads();
    for (int s = 128; s > 0; s >>= 1) {
        if (tid < s) red[tid] += red[tid + s];
        __syncthreads();
    }
    if (tid == 0) g_Z = red[0];

    for (int i = tid; i < NBINS; i += 256) sh[i] = g_hist[i];
    __syncthreads();
    unsigned cs = 0;
    #pragma unroll
    for (int j = 0; j < 32; j++) cs += sh[tid * 32 + j];
    chunk[tid] = cs;
    __syncthreads();

    if (tid == 0) {
        unsigned target = (unsigned)(N < KSEL ? N : KSEL);
        unsigned cum = 0;
        int c = 0;
        while (c < 256 && cum + chunk[c] < target) { cum += chunk[c]; c++; }
        int b;
        if (c == 256) b = NBINS - 1;
        else {
            b = c * 32;
            while (b < (c + 1) * 32 && cum + sh[b] < target) { cum += sh[b]; b++; }
            if (b >= NBINS) b = NBINS - 1;
        }
        g_bin_thresh = b;
        g_done1 = 0;                 // reset for next graph replay
    }
}

// ============================================================================
// Kernel 2: compact candidates, last block: bitonic top-K + output + reset.
// ============================================================================
__global__ void k_sel(const float* __restrict__ y, float* __restrict__ out,
                      int N, int DY) {
    // 32 KB shared region: bitonic keys (16 KB used) OR fallback merge arrays.
    __shared__ unsigned long long sk[SORT_CAP * 2];  // 32 KB (aliased by fallback)
    __shared__ float w[KSEL];
    __shared__ int   widx[KSEL];
    __shared__ float sZ;
    __shared__ bool  amLast;

    int tid = threadIdx.x;
    unsigned limit = ((unsigned)(g_bin_thresh + 1)) << BSHIFT;  // bits < limit <=> bin <= thresh

    int n4 = N >> 2;
    const float4* d4 = (const float4*)g_dist;
    for (int i = blockIdx.x * blockDim.x + tid; i < n4;
         i += gridDim.x * blockDim.x) {
        float4 v = d4[i];
        if (__float_as_uint(v.x) < limit) { int p = atomicAdd(&g_ncand, 1); if (p < CAND_CAP) { g_cd[p] = v.x; g_ci[p] = 4 * i;     } }
        if (__float_as_uint(v.y) < limit) { int p = atomicAdd(&g_ncand, 1); if (p < CAND_CAP) { g_cd[p] = v.y; g_ci[p] = 4 * i + 1; } }
        if (__float_as_uint(v.z) < limit) { int p = atomicAdd(&g_ncand, 1); if (p < CAND_CAP) { g_cd[p] = v.z; g_ci[p] = 4 * i + 2; } }
        if (__float_as_uint(v.w) < limit) { int p = atomicAdd(&g_ncand, 1); if (p < CAND_CAP) { g_cd[p] = v.w; g_ci[p] = 4 * i + 3; } }
    }
    if (blockIdx.x == 0 && tid == 0) {           // scalar tail (N % 4)
        for (int i = n4 * 4; i < N; i++) {
            float d = g_dist[i];
            if (__float_as_uint(d) < limit) {
                int p = atomicAdd(&g_ncand, 1);
                if (p < CAND_CAP) { g_cd[p] = d; g_ci[p] = i; }
            }
        }
    }

    __threadfence();
    if (tid == 0) amLast = (atomicAdd(&g_done2, 1u) == (unsigned)gridDim.x - 1u);
    __syncthreads();
    if (!amLast) return;

    if (tid == 0) sZ = g_Z;
    int ncand = g_ncand;
    if (ncand > CAND_CAP) ncand = CAND_CAP;
    __syncthreads();

    if (ncand <= SORT_CAP) {
        // ---- common path: u64 bitonic sort, key = (dist_bits<<32)|idx ----
        // Ascending sort => smallest distances first; idx in low bits gives
        // jax top_k's lower-index-first tie-break. Deterministic regardless
        // of the nondeterministic compaction order (keys are unique).
        int sort_n = 64;
        while (sort_n < ncand) sort_n <<= 1;     // <= SORT_CAP

        for (int i = tid; i < sort_n; i += blockDim.x)
            sk[i] = (i < ncand)
                ? ((unsigned long long)__float_as_uint(g_cd[i]) << 32) | (unsigned)g_ci[i]
                : ~0ull;
        __syncthreads();

        for (int k = 2; k <= sort_n; k <<= 1) {
            for (int j = k >> 1; j > 0; j >>= 1) {
                for (int i = tid; i < sort_n; i += blockDim.x) {
                    int ixj = i ^ j;
                    if (ixj > i) {
                        unsigned long long a = sk[i], b = sk[ixj];
                        bool up = ((i & k) == 0);
                        if (up ? (a > b) : (a < b)) { sk[i] = b; sk[ixj] = a; }
                    }
                }
                __syncthreads();
            }
        }

        if (tid < KSEL) {
            unsigned long long key = sk[tid];
            if (tid < ncand && key != ~0ull) {
                float d = __uint_as_float((unsigned)(key >> 32));
                w[tid] = expf(-d) / sZ;
                widx[tid] = (int)(unsigned)(key & 0xffffffffu);
            } else {
                w[tid] = 0.0f;
                widx[tid] = -1;
            }
        }
    } else {
        // ---- fallback (ncand > SORT_CAP; not expected): serial merge path ----
        float* md = (float*)sk;                   // MERGE_T*KSEL floats = 16 KB
        int*   mi = (int*)(sk + SORT_CAP);        // MERGE_T*KSEL ints   = 16 KB

        float td[KSEL];
        int   ti[KSEL];
        if (tid < MERGE_T) {
            #pragma unroll
            for (int k = 0; k < KSEL; k++) { td[k] = FLT_MAX; ti[k] = 0x7fffffff; }
            for (int i = tid; i < ncand; i += MERGE_T) {
                float d = g_cd[i];
                int id = g_ci[i];
                if (d < td[KSEL - 1] || (d == td[KSEL - 1] && id < ti[KSEL - 1])) {
                    int pos = KSEL - 1;
                    while (pos > 0 &&
                           (td[pos - 1] > d || (td[pos - 1] == d && ti[pos - 1] > id))) {
                        td[pos] = td[pos - 1]; ti[pos] = ti[pos - 1]; pos--;
                    }
                    td[pos] = d; ti[pos] = id;
                }
            }
            #pragma unroll
            for (int k = 0; k < KSEL; k++) {
                md[tid * KSEL + k] = td[k];
                mi[tid * KSEL + k] = ti[k];
            }
        }
        __syncthreads();

        for (int stride = 1; stride < MERGE_T; stride <<= 1) {
            if (tid < MERGE_T && (tid & (2 * stride - 1)) == 0) {
                int p = tid * KSEL;
                int qq = (tid + stride) * KSEL;
                float od[KSEL];
                int   oi[KSEL];
                int ip = 0, iq = 0;
                #pragma unroll
                for (int k = 0; k < KSEL; k++) {
                    float dp = md[p + ip], dq = md[qq + iq];
                    int   jp = mi[p + ip], jq = mi[qq + iq];
                    bool takep = (dp < dq) || (dp == dq && jp <= jq);
                    if (takep) { od[k] = dp; oi[k] = jp; ip++; }
                    else       { od[k] = dq; oi[k] = jq; iq++; }
                }
                #pragma unroll
                for (int k = 0; k < KSEL; k++) { md[p + k] = od[k]; mi[p + k] = oi[k]; }
            }
            __syncthreads();
        }

        if (tid < KSEL) {
            float d = md[tid];
            w[tid] = (d < FLT_MAX) ? expf(-d) / sZ : 0.0f;
            widx[tid] = mi[tid];
        }
    }
    __syncthreads();

    // ---- weighted gather of y rows ----
    for (int j = tid; j < DY; j += blockDim.x) {
        float acc = 0.0f;
        #pragma unroll
        for (int k = 0; k < KSEL; k++) {
            int id = widx[k];
            if ((unsigned)id < (unsigned)N)
                acc += w[k] * y[(size_t)id * DY + j];
        }
        out[j] = acc;
    }

    // ---- reset scratch for next graph replay ----
    for (int i = tid; i < NBINS; i += blockDim.x) g_hist[i] = 0u;
    if (tid == 0) { g_ncand = 0; g_done2 = 0; }
}

// ---------------------------------------------------------------- host
extern "C" void kernel_launch(void* const* d_in, const int* in_sizes, int n_in,
                              void* d_out, int out_size) {
    const float* X = (const float*)d_in[0];
    const float* y = (const float*)d_in[1];
    const float* q = (const float*)d_in[2];

    int D  = in_sizes[2];
    int N  = in_sizes[0] / D;
    int DY = in_sizes[1] / N;
    float* out = (float*)d_out;

    int b1 = 1536;
    int need1 = (D == 64) ? (N + 63) / 64 : (N + 255) / 256;
    if (need1 < b1) b1 = need1;
    if (b1 < 1) b1 = 1;
    if (b1 > MAXBLK) b1 = MAXBLK;

    int b2 = 512;
    int need2 = (N / 4 + 255) / 256;
    if (need2 < b2) b2 = need2;
    if (b2 < 1) b2 = 1;

    k_dist<<<b1, 256>>>(X, q, N, D);
    k_sel<<<b2, 256>>>(y, out, N, DY);
}

// round 11
// speedup vs baseline: 1.7603x; 1.1795x over previous
#include <cuda_runtime.h>
#include <math.h>
#include <float.h>

#define MAXN      (1 << 20)   // dist scratch capacity (N = 1e6 fits)
#define CAND_CAP  65536
#define KSEL      32
#define NBINS     8192        // coarse bins = float_bits(d) >> 18 (monotone, d >= 0)
#define BSHIFT    18
#define FSHIFT    8           // fine bins: 256-ulp wide, 1024 per coarse bin
#define NFINE     1024
#define MAXBLK    4096
#define SORT_CAP  2048        // final bitonic capacity (u64 keys, 16 KB)

// ---- scratch (static device globals; zero-initialized at module load) ----
__device__ float    g_dist[MAXN];
__device__ float    g_partsum[MAXBLK];
__device__ unsigned g_hist[NBINS];     // zero-init; reset by k_sel last block
__device__ float    g_Z;
__device__ int      g_bin_thresh;
__device__ int      g_ncand;           // zero-init; reset by k_sel last block
__device__ float    g_cd[CAND_CAP];
__device__ int      g_ci[CAND_CAP];
__device__ unsigned g_done1;           // zero-init; reset by k_dist last block
__device__ unsigned g_done2;           // zero-init; reset by k_sel last block

// ============================================================================
// Kernel 1: distances (coalesced, 16 rows/warp-iter), exp-sum partials,
// 16-bit-packed shared histogram. Last block: Z reduce + coarse threshold bin.
// ============================================================================
__global__ void k_dist(const float* __restrict__ X, const float* __restrict__ q,
                       int N, int D) {
    __shared__ unsigned hist16[NBINS / 2];   // 16 KB packed block histogram
    __shared__ float4   sq4[16];
    __shared__ float    red[256];
    __shared__ unsigned chunk[256];          // 32 coarse bins each
    __shared__ unsigned super[32];           // 8 chunks each
    __shared__ unsigned binv[32];
    __shared__ int      sel_chunk;
    __shared__ unsigned cum_at_chunk;
    __shared__ bool     amLast;

    int tid = threadIdx.x;
    for (int i = tid; i < NBINS / 2; i += 256) hist16[i] = 0u;
    if (D == 64 && tid < 16) sq4[tid] = ((const float4*)q)[tid];
    __syncthreads();

    float lsum = 0.0f;

    if (D == 64) {
        int lane = tid & 31;
        int wid  = blockIdx.x * (blockDim.x >> 5) + (tid >> 5);
        int nw   = gridDim.x * (blockDim.x >> 5);
        int col  = lane & 15;      // 16 lanes cover one 64-float row
        int half = lane >> 4;      // two rows per LDG.128
        float4 qv = sq4[col];

        for (int base = wid * 16; base < N; base += nw * 16) {
            float4 v[8];
            float  acc[8];
            #pragma unroll
            for (int u = 0; u < 8; u++) {          // 8 loads batched in flight
                int row = base + 2 * u + half;
                v[u] = qv;                          // OOB => zero diff (unused)
                if (row < N)
                    v[u] = *(const float4*)(X + (size_t)row * 64 + col * 4);
            }
            #pragma unroll
            for (int u = 0; u < 8; u++) {
                float d0 = v[u].x - qv.x, d1 = v[u].y - qv.y;
                float d2 = v[u].z - qv.z, d3 = v[u].w - qv.w;
                acc[u] = d0 * d0 + d1 * d1 + d2 * d2 + d3 * d3;
            }
            #pragma unroll
            for (int u = 0; u < 8; u++) {          // independent shfl chains
                acc[u] += __shfl_xor_sync(0xffffffffu, acc[u], 8);
                acc[u] += __shfl_xor_sync(0xffffffffu, acc[u], 4);
                acc[u] += __shfl_xor_sync(0xffffffffu, acc[u], 2);
                acc[u] += __shfl_xor_sync(0xffffffffu, acc[u], 1);
            }
            if (col == 0) {
                #pragma unroll
                for (int u = 0; u < 8; u++) {
                    int row = base + 2 * u + half;
                    if (row < N) {
                        float d = sqrtf(acc[u]);
                        g_dist[row] = d;
                        lsum += expf(-d);           // TAU = 1
                        unsigned b = __float_as_uint(d) >> BSHIFT;
                        atomicAdd(&hist16[b >> 1], 1u << ((b & 1) * 16));
                    }
                }
            }
        }
    } else {
        for (int i = blockIdx.x * blockDim.x + tid; i < N;
             i += gridDim.x * blockDim.x) {
            float acc = 0.0f;
            const float* xr = X + (size_t)i * D;
            for (int j = 0; j < D; j++) { float d = xr[j] - q[j]; acc += d * d; }
            float d = sqrtf(acc);
            g_dist[i] = d;
            lsum += expf(-d);
            unsigned b = __float_as_uint(d) >> BSHIFT;
            atomicAdd(&hist16[b >> 1], 1u << ((b & 1) * 16));
        }
    }

    // block Z partial (deterministic)
    red[tid] = lsum;
    __syncthreads();
    for (int s = 128; s > 0; s >>= 1) {
        if (tid < s) red[tid] += red[tid + s];
        __syncthreads();
    }
    if (tid == 0) g_partsum[blockIdx.x] = red[0];

    // flush packed histogram
    for (int i = tid; i < NBINS / 2; i += 256) {
        unsigned v = hist16[i];
        unsigned lo = v & 0xffffu, hi = v >> 16;
        if (lo) atomicAdd(&g_hist[2 * i],     lo);
        if (hi) atomicAdd(&g_hist[2 * i + 1], hi);
    }

    // ---- last-block tail ----
    __threadfence();
    if (tid == 0) amLast = (atomicAdd(&g_done1, 1u) == (unsigned)gridDim.x - 1u);
    __syncthreads();
    if (!amLast) return;

    float s2 = 0.0f;
    for (int i = tid; i < gridDim.x; i += 256) s2 += g_partsum[i];
    red[tid] = s2;
    __syncthreads();
    for (int s = 128; s > 0; s >>= 1) {
        if (tid < s) red[tid] += red[tid + s];
        __syncthreads();
    }
    if (tid == 0) g_Z = red[0];

    // 3-level coarse threshold scan: chunk(32 bins) -> super(8 chunks) -> bins
    unsigned cs = 0;
    for (int j = 0; j < 32; j++) cs += g_hist[tid * 32 + j];
    chunk[tid] = cs;
    __syncthreads();
    if (tid < 32) {
        unsigned s = 0;
        #pragma unroll
        for (int j = 0; j < 8; j++) s += chunk[tid * 8 + j];
        super[tid] = s;
    }
    __syncthreads();
    if (tid == 0) {
        unsigned target = (unsigned)(N < KSEL ? N : KSEL);
        unsigned cum = 0;
        int si = 0;
        while (si < 31 && cum + super[si] < target) { cum += super[si]; si++; }
        int c = si * 8;
        while (c < si * 8 + 7 && cum + chunk[c] < target) { cum += chunk[c]; c++; }
        sel_chunk = c;
        cum_at_chunk = cum;
    }
    __syncthreads();
    if (tid < 32) binv[tid] = g_hist[sel_chunk * 32 + tid];
    __syncthreads();
    if (tid == 0) {
        unsigned target = (unsigned)(N < KSEL ? N : KSEL);
        unsigned cum = cum_at_chunk;
        int b = sel_chunk * 32;
        int j = 0;
        while (j < 31 && cum + binv[j] < target) { cum += binv[j]; j++; b++; }
        if (b >= NBINS) b = NBINS - 1;
        g_bin_thresh = b;
        g_done1 = 0;                 // reset for next graph replay
    }
}

// ============================================================================
// Kernel 2: compact coarse candidates; last block: fine refinement (exact
// 256-ulp threshold) -> tiny bitonic sort -> weights/output -> scratch reset.
// ============================================================================
__global__ void k_sel(const float* __restrict__ y, float* __restrict__ out,
                      int N, int DY) {
    __shared__ unsigned long long skey[SORT_CAP];   // 16 KB final sort keys
    __shared__ unsigned fine[NFINE];                // 4 KB fine histogram
    __shared__ unsigned fchunk[256];
    __shared__ unsigned fsuper[32];
    __shared__ int      s_below, s_cnt2;
    __shared__ unsigned s_limit2;
    __shared__ float    w[KSEL];
    __shared__ int      widx[KSEL];
    __shared__ float    sZ;
    __shared__ bool     amLast;

    int tid = threadIdx.x;
    int bt = g_bin_thresh;
    unsigned limit = ((unsigned)(bt + 1)) << BSHIFT;   // bits < limit <=> bin <= bt

    int n4 = N >> 2;
    const float4* d4 = (const float4*)g_dist;
    for (int i = blockIdx.x * blockDim.x + tid; i < n4;
         i += gridDim.x * blockDim.x) {
        float4 v = d4[i];
        if (__float_as_uint(v.x) < limit) { int p = atomicAdd(&g_ncand, 1); if (p < CAND_CAP) { g_cd[p] = v.x; g_ci[p] = 4 * i;     } }
        if (__float_as_uint(v.y) < limit) { int p = atomicAdd(&g_ncand, 1); if (p < CAND_CAP) { g_cd[p] = v.y; g_ci[p] = 4 * i + 1; } }
        if (__float_as_uint(v.z) < limit) { int p = atomicAdd(&g_ncand, 1); if (p < CAND_CAP) { g_cd[p] = v.z; g_ci[p] = 4 * i + 2; } }
        if (__float_as_uint(v.w) < limit) { int p = atomicAdd(&g_ncand, 1); if (p < CAND_CAP) { g_cd[p] = v.w; g_ci[p] = 4 * i + 3; } }
    }
    if (blockIdx.x == 0 && tid == 0) {                 // scalar tail (N % 4)
        for (int i = n4 * 4; i < N; i++) {
            float d = g_dist[i];
            if (__float_as_uint(d) < limit) {
                int p = atomicAdd(&g_ncand, 1);
                if (p < CAND_CAP) { g_cd[p] = d; g_ci[p] = i; }
            }
        }
    }

    __threadfence();
    if (tid == 0) amLast = (atomicAdd(&g_done2, 1u) == (unsigned)gridDim.x - 1u);
    __syncthreads();
    if (!amLast) return;

    // ---------------- last block: exact selection ----------------
    if (tid == 0) { sZ = g_Z; s_below = 0; s_cnt2 = 0; }
    for (int i = tid; i < NFINE; i += 256) fine[i] = 0u;
    __syncthreads();

    int ncand = g_ncand;
    if (ncand > CAND_CAP) ncand = CAND_CAP;
    unsigned base = ((unsigned)bt) << BSHIFT;
    unsigned target = (unsigned)(N < KSEL ? N : KSEL);

    // fine histogram of candidates within the coarse threshold bin
    for (int i = tid; i < ncand; i += 256) {
        unsigned bits = __float_as_uint(g_cd[i]);
        if (bits < base) atomicAdd((unsigned*)&s_below, 1u);
        else             atomicAdd(&fine[(bits - base) >> FSHIFT], 1u);
    }
    __syncthreads();

    // 3-level fine prefix: fchunk(4 bins) -> fsuper(8 chunks) -> bins
    {
        unsigned c = fine[tid * 4] + fine[tid * 4 + 1] +
                     fine[tid * 4 + 2] + fine[tid * 4 + 3];
        fchunk[tid] = c;
    }
    __syncthreads();
    if (tid < 32) {
        unsigned s = 0;
        #pragma unroll
        for (int j = 0; j < 8; j++) s += fchunk[tid * 8 + j];
        fsuper[tid] = s;
    }
    __syncthreads();
    if (tid == 0) {
        unsigned cum = (unsigned)s_below;
        int si = 0;
        while (si < 31 && cum + fsuper[si] < target) { cum += fsuper[si]; si++; }
        int c = si * 8;
        while (c < si * 8 + 7 && cum + fchunk[c] < target) { cum += fchunk[c]; c++; }
        int f = c * 4;
        while (f < c * 4 + 3 && cum + fine[f] < target) { cum += fine[f]; f++; }
        if (f >= NFINE) f = NFINE - 1;
        s_limit2 = base + ((unsigned)(f + 1) << FSHIFT);
    }
    __syncthreads();

    // compact survivors (expected ~target + O(fine-bin count) ~ 40-80)
    unsigned limit2 = s_limit2;
    for (int i = tid; i < ncand; i += 256) {
        unsigned bits = __float_as_uint(g_cd[i]);
        if (bits < limit2) {
            int p = atomicAdd(&s_cnt2, 1);
            if (p < SORT_CAP)
                skey[p] = ((unsigned long long)bits << 32) | (unsigned)g_ci[i];
        }
    }
    __syncthreads();

    int cnt2 = s_cnt2;
    if (cnt2 > SORT_CAP) cnt2 = SORT_CAP;
    int sort_n = 64;
    while (sort_n < cnt2) sort_n <<= 1;
    for (int i = tid; i < sort_n; i += 256)
        if (i >= cnt2) skey[i] = ~0ull;
    __syncthreads();

    // bitonic sort ascending: key = (dist_bits<<32)|idx — matches jax top_k
    // ordering incl. lower-index-first tie-break; deterministic.
    for (int k = 2; k <= sort_n; k <<= 1) {
        for (int j = k >> 1; j > 0; j >>= 1) {
            for (int i = tid; i < sort_n; i += 256) {
                int ixj = i ^ j;
                if (ixj > i) {
                    unsigned long long a = skey[i], b = skey[ixj];
                    bool up = ((i & k) == 0);
                    if (up ? (a > b) : (a < b)) { skey[i] = b; skey[ixj] = a; }
                }
            }
            __syncthreads();
        }
    }

    if (tid < KSEL) {
        unsigned long long key = skey[tid];
        if (tid < cnt2 && key != ~0ull) {
            float d = __uint_as_float((unsigned)(key >> 32));
            w[tid] = expf(-d) / sZ;
            widx[tid] = (int)(unsigned)(key & 0xffffffffu);
        } else {
            w[tid] = 0.0f;
            widx[tid] = -1;
        }
    }
    __syncthreads();

    // weighted gather of y rows
    for (int j = tid; j < DY; j += blockDim.x) {
        float acc = 0.0f;
        #pragma unroll
        for (int k = 0; k < KSEL; k++) {
            int id = widx[k];
            if ((unsigned)id < (unsigned)N)
                acc += w[k] * y[(size_t)id * DY + j];
        }
        out[j] = acc;
    }

    // reset scratch for next graph replay
    for (int i = tid; i < NBINS; i += blockDim.x) g_hist[i] = 0u;
    if (tid == 0) { g_ncand = 0; g_done2 = 0; }
}

// ---------------------------------------------------------------- host
extern "C" void kernel_launch(void* const* d_in, const int* in_sizes, int n_in,
                              void* d_out, int out_size) {
    const float* X = (const float*)d_in[0];
    const float* y = (const float*)d_in[1];
    const float* q = (const float*)d_in[2];

    int D  = in_sizes[2];
    int N  = in_sizes[0] / D;
    int DY = in_sizes[1] / N;
    float* out = (float*)d_out;

    int b1;
    if (D == 64) {
        b1 = 1184;                                // 148 SMs x 8 blocks
        int need = (N + 127) / 128;               // 8 warps x 16 rows per block-iter
        if (need < b1) b1 = need;
    } else {
        b1 = (N + 255) / 256;
        if (b1 > 1184) b1 = 1184;
    }
    if (b1 < 1) b1 = 1;
    if (b1 > MAXBLK) b1 = MAXBLK;

    int b2 = (N / 4 + 255) / 256;
    if (b2 > 1024) b2 = 1024;
    if (b2 < 1) b2 = 1;

    k_dist<<<b1, 256>>>(X, q, N, D);
    k_sel<<<b2, 256>>>(y, out, N, DY);
}